// round 4
// baseline (speedup 1.0000x reference)
#include <cuda_runtime.h>
#include <cuda_bf16.h>
#include <cstdint>

// Problem shape
#define NB   256
#define NH   512
#define NW   512
#define HW   (NH * NW)          // 262144 = 1<<18
#define NTOT ((size_t)NB * HW)  // 67108864
#define BPB  8                  // blocks per batch in pass 1
#define K1_BLOCKS (NB * BPB)    // 2048
#define CHUNK (HW / BPB)        // 32768 elems per block
#define FWHM 0.5f
#define DHW  32                 // h/H_SCALE = w/W_SCALE = 512/16

// Scratch (no allocations allowed — __device__ globals)
__device__ unsigned long long g_maxkey[NB];
__device__ double g_part1[K1_BLOCKS];
__device__ double g_part2[NB];

// ---------------------------------------------------------------------------
// Kernel 0: reset per-batch argmax keys (partials are fully overwritten).
// ---------------------------------------------------------------------------
__global__ void init_kernel() {
    g_maxkey[threadIdx.x] = 0ull;
}

// ---------------------------------------------------------------------------
// Kernel 1: fused unweighted sum of squared diffs + per-batch first-argmax.
// key = (float_bits(val) << 32) | (0xFFFFFFFF - idx)
//   target in [0,1) => non-negative => uint bit order == float order.
//   Larger (~idx) under max => smallest index wins ties (first-max).
// ---------------------------------------------------------------------------
__global__ __launch_bounds__(256, 8)
void pass1_kernel(const float* __restrict__ outp, const float* __restrict__ tgtp) {
    const int batch = blockIdx.x >> 3;        // / BPB
    const int chunk = blockIdx.x & (BPB - 1);
    const size_t base = (size_t)batch * HW + (size_t)chunk * CHUNK;
    const float4* __restrict__ o4 = (const float4*)(outp + base);
    const float4* __restrict__ t4 = (const float4*)(tgtp + base);
    const unsigned idx0 = (unsigned)(chunk * CHUNK);

    float s = 0.0f;
    unsigned long long bk = 0ull;

    #pragma unroll 4
    for (int i = threadIdx.x; i < CHUNK / 4; i += 256) {
        float4 t = t4[i];
        float4 o = o4[i];
        float d0 = o.x - t.x, d1 = o.y - t.y, d2 = o.z - t.z, d3 = o.w - t.w;
        s += d0 * d0 + d1 * d1 + d2 * d2 + d3 * d3;

        unsigned eb = idx0 + 4u * (unsigned)i;
        unsigned long long k0 = ((unsigned long long)__float_as_uint(t.x) << 32) | (0xFFFFFFFFu - (eb + 0u));
        unsigned long long k1 = ((unsigned long long)__float_as_uint(t.y) << 32) | (0xFFFFFFFFu - (eb + 1u));
        unsigned long long k2 = ((unsigned long long)__float_as_uint(t.z) << 32) | (0xFFFFFFFFu - (eb + 2u));
        unsigned long long k3 = ((unsigned long long)__float_as_uint(t.w) << 32) | (0xFFFFFFFFu - (eb + 3u));
        if (k0 > bk) bk = k0;
        if (k1 > bk) bk = k1;
        if (k2 > bk) bk = k2;
        if (k3 > bk) bk = k3;
    }

    // intra-warp reduce
    #pragma unroll
    for (int off = 16; off > 0; off >>= 1) {
        s += __shfl_down_sync(0xFFFFFFFFu, s, off);
        unsigned long long ok = __shfl_down_sync(0xFFFFFFFFu, bk, off);
        if (ok > bk) bk = ok;
    }

    __shared__ float ssum[8];
    __shared__ unsigned long long skey[8];
    const int w = threadIdx.x >> 5, l = threadIdx.x & 31;
    if (l == 0) { ssum[w] = s; skey[w] = bk; }
    __syncthreads();

    if (threadIdx.x < 8) {
        s = ssum[threadIdx.x];
        bk = skey[threadIdx.x];
        #pragma unroll
        for (int off = 4; off > 0; off >>= 1) {
            s += __shfl_down_sync(0xFFu, s, off);
            unsigned long long ok = __shfl_down_sync(0xFFu, bk, off);
            if (ok > bk) bk = ok;
        }
        if (threadIdx.x == 0) {
            g_part1[blockIdx.x] = (double)s;
            atomicMax(&g_maxkey[batch], bk);   // order-independent => deterministic
        }
    }
}

// ---------------------------------------------------------------------------
// Kernel 2: window fix-up. One block per batch; add sqdiff*(vh*vw - 1)
// over the <=64x64 ramp window (only when max >= FWHM threshold).
// ---------------------------------------------------------------------------
__global__ __launch_bounds__(256)
void pass2_kernel(const float* __restrict__ outp, const float* __restrict__ tgtp) {
    const int b = blockIdx.x;
    const unsigned long long key = g_maxkey[b];
    const float mv = __uint_as_float((unsigned)(key >> 32));

    float s = 0.0f;
    if (mv >= FWHM) {
        const unsigned pos = 0xFFFFFFFFu - (unsigned)(key & 0xFFFFFFFFu);
        const int ph = (int)(pos >> 9);      // pos / 512
        const int pw = (int)(pos & 511u);
        const int top  = max(ph - DHW, 0);
        const int bot  = min(ph + DHW, NH);
        const int left = max(pw - DHW, 0);
        const int right= min(pw + DHW, NW);
        const int Lh = bot - top, Lw = right - left;
        const float dh = (float)max((Lh + 1) / 2 - 1, 1);
        const float dw = (float)max((Lw + 1) / 2 - 1, 1);
        const int total = Lh * Lw;
        const size_t base = (size_t)b << 18;

        for (int i = threadIdx.x; i < total; i += 256) {
            const int r = i / Lw, c = i - r * Lw;
            const int row = top + r, col = left + c;
            const int kh = min(r, Lh - 1 - r);
            const int kw = min(c, Lw - 1 - c);
            const float vh = 1.0f + 9.0f * (float)kh / dh;
            const float vw = 1.0f + 9.0f * (float)kw / dw;
            const size_t idx = base + ((size_t)row << 9) + (size_t)col;
            const float d = outp[idx] - tgtp[idx];
            s += d * d * (vh * vw - 1.0f);
        }
    }

    // block reduce (fixed order => deterministic)
    #pragma unroll
    for (int off = 16; off > 0; off >>= 1)
        s += __shfl_down_sync(0xFFFFFFFFu, s, off);
    __shared__ float ssum[8];
    const int w = threadIdx.x >> 5, l = threadIdx.x & 31;
    if (l == 0) ssum[w] = s;
    __syncthreads();
    if (threadIdx.x == 0) {
        float t = 0.0f;
        #pragma unroll
        for (int i = 0; i < 8; i++) t += ssum[i];
        g_part2[b] = (double)t;
    }
}

// ---------------------------------------------------------------------------
// Kernel 3: deterministic final reduction + mean.
// ---------------------------------------------------------------------------
__global__ void finalize_kernel(float* __restrict__ out) {
    __shared__ double sh[256];
    double s = 0.0;
    for (int i = threadIdx.x; i < K1_BLOCKS; i += 256) s += g_part1[i];
    s += g_part2[threadIdx.x];
    sh[threadIdx.x] = s;
    __syncthreads();
    #pragma unroll
    for (int st = 128; st > 0; st >>= 1) {
        if (threadIdx.x < st) sh[threadIdx.x] += sh[threadIdx.x + st];
        __syncthreads();
    }
    if (threadIdx.x == 0)
        out[0] = (float)(sh[0] * (1.0 / (double)NTOT));
}

extern "C" void kernel_launch(void* const* d_in, const int* in_sizes, int n_in,
                              void* d_out, int out_size) {
    const float* outp = (const float*)d_in[0];   // "output" (normal)
    const float* tgtp = (const float*)d_in[1];   // "target" (uniform)
    float* res = (float*)d_out;

    init_kernel<<<1, NB>>>();
    pass1_kernel<<<K1_BLOCKS, 256>>>(outp, tgtp);
    pass2_kernel<<<NB, 256>>>(outp, tgtp);
    finalize_kernel<<<1, 256>>>(res);
}

// round 5
// speedup vs baseline: 1.0254x; 1.0254x over previous
#include <cuda_runtime.h>
#include <cuda_bf16.h>
#include <cstdint>

// Problem shape
#define NB   256
#define NH   512
#define NW   512
#define HW   (NH * NW)          // 262144 = 1<<18
#define NTOT ((size_t)NB * HW)  // 67108864
#define BPB  4                  // blocks per batch in pass 1
#define K1_BLOCKS (NB * BPB)    // 1024  (single wave: 1024 < 148*7)
#define CHUNK (HW / BPB)        // 65536 elems per block
#define FWHM 0.5f
#define DHW  32                 // h/H_SCALE = w/W_SCALE = 512/16

// Scratch (no allocations allowed — __device__ globals)
__device__ unsigned long long g_keyblk[K1_BLOCKS];  // per-block argmax key (plain store)
__device__ double   g_part1[K1_BLOCKS];
__device__ double   g_part2[NB];
__device__ unsigned g_done;                          // zero at load; last block resets

// ---------------------------------------------------------------------------
// Pass 1: fused unweighted sum of squared diffs + per-block first-argmax.
// Cheap loop: float max via FMNMX + rare strict-greater branch recording
// (value, first index). 64-bit key built once per lane at reduce time:
//   key = (float_bits(val) << 32) | (0xFFFFFFFF - idx)
// target in [0,1) => non-negative => uint bit order == float order;
// larger ~idx under max => smallest index wins ties (first-max).
// ---------------------------------------------------------------------------
__global__ __launch_bounds__(256)
void pass1_kernel(const float* __restrict__ outp, const float* __restrict__ tgtp) {
    const int batch = blockIdx.x >> 2;        // / BPB
    const int chunk = blockIdx.x & (BPB - 1);
    const size_t base = (size_t)batch * HW + (size_t)chunk * CHUNK;
    const float4* __restrict__ o4 = (const float4*)(outp + base);
    const float4* __restrict__ t4 = (const float4*)(tgtp + base);
    const unsigned idx0 = (unsigned)(chunk * CHUNK);

    float s = 0.0f;
    float mval = -1.0f;          // target >= 0, so any real value beats this
    unsigned midx = 0u;

    #pragma unroll 4
    for (int i = threadIdx.x; i < CHUNK / 4; i += 256) {
        float4 t = t4[i];
        float4 o = o4[i];
        float d0 = o.x - t.x, d1 = o.y - t.y, d2 = o.z - t.z, d3 = o.w - t.w;
        s += d0 * d0 + d1 * d1 + d2 * d2 + d3 * d3;

        float m01 = fmaxf(t.x, t.y);
        float m23 = fmaxf(t.z, t.w);
        float m4  = fmaxf(m01, m23);
        if (m4 > mval) {                       // rare after warmup
            mval = m4;
            unsigned eb = idx0 + 4u * (unsigned)i;
            midx = (t.x == m4) ? eb
                 : (t.y == m4) ? eb + 1u
                 : (t.z == m4) ? eb + 2u
                 :               eb + 3u;      // in-quad first-match tie-break
        }
    }

    // Build 64-bit key once per lane, then warp max-reduce (sum alongside).
    unsigned long long bk =
        ((unsigned long long)__float_as_uint(mval) << 32) | (0xFFFFFFFFu - midx);

    #pragma unroll
    for (int off = 16; off > 0; off >>= 1) {
        s += __shfl_down_sync(0xFFFFFFFFu, s, off);
        unsigned long long ok = __shfl_down_sync(0xFFFFFFFFu, bk, off);
        if (ok > bk) bk = ok;
    }

    __shared__ float ssum[8];
    __shared__ unsigned long long skey[8];
    const int w = threadIdx.x >> 5, l = threadIdx.x & 31;
    if (l == 0) { ssum[w] = s; skey[w] = bk; }
    __syncthreads();

    if (threadIdx.x < 8) {
        s  = ssum[threadIdx.x];
        bk = skey[threadIdx.x];
        #pragma unroll
        for (int off = 4; off > 0; off >>= 1) {
            s += __shfl_down_sync(0xFFu, s, off);
            unsigned long long ok = __shfl_down_sync(0xFFu, bk, off);
            if (ok > bk) bk = ok;
        }
        if (threadIdx.x == 0) {
            g_part1[blockIdx.x]  = (double)s;
            g_keyblk[blockIdx.x] = bk;     // plain store — no init kernel needed
        }
    }
}

// ---------------------------------------------------------------------------
// Pass 2 (+ fused finalize): one block per batch. Reduce the batch's 4 keys,
// add sqdiff*(vh*vw - 1) over the <=64x64 ramp window when max >= threshold.
// The LAST block to finish sums all (L2-warm) partials and writes the mean.
// ---------------------------------------------------------------------------
__global__ __launch_bounds__(256)
void pass2_kernel(const float* __restrict__ outp, const float* __restrict__ tgtp,
                  float* __restrict__ res) {
    const int b = blockIdx.x;

    unsigned long long key = g_keyblk[4 * b];
    #pragma unroll
    for (int j = 1; j < 4; j++) {
        unsigned long long k = g_keyblk[4 * b + j];
        if (k > key) key = k;
    }
    const float mv = __uint_as_float((unsigned)(key >> 32));

    float s = 0.0f;
    if (mv >= FWHM) {
        const unsigned pos = 0xFFFFFFFFu - (unsigned)(key & 0xFFFFFFFFu);
        const int ph = (int)(pos >> 9);      // pos / 512
        const int pw = (int)(pos & 511u);
        const int top   = max(ph - DHW, 0);
        const int bot   = min(ph + DHW, NH);
        const int left  = max(pw - DHW, 0);
        const int right = min(pw + DHW, NW);
        const int Lh = bot - top, Lw = right - left;
        const float dh = (float)max((Lh + 1) / 2 - 1, 1);
        const float dw = (float)max((Lw + 1) / 2 - 1, 1);
        const int total = Lh * Lw;
        const size_t bbase = (size_t)b << 18;

        for (int i = threadIdx.x; i < total; i += 256) {
            const int r = i / Lw, c = i - r * Lw;
            const int row = top + r, col = left + c;
            const int kh = min(r, Lh - 1 - r);
            const int kw = min(c, Lw - 1 - c);
            const float vh = 1.0f + 9.0f * (float)kh / dh;
            const float vw = 1.0f + 9.0f * (float)kw / dw;
            const size_t idx = bbase + ((size_t)row << 9) + (size_t)col;
            const float d = outp[idx] - tgtp[idx];
            s += d * d * (vh * vw - 1.0f);
        }
    }

    // block reduce (fixed order => deterministic)
    #pragma unroll
    for (int off = 16; off > 0; off >>= 1)
        s += __shfl_down_sync(0xFFFFFFFFu, s, off);
    __shared__ float ssum[8];
    __shared__ int slast;
    const int w = threadIdx.x >> 5, l = threadIdx.x & 31;
    if (l == 0) ssum[w] = s;
    __syncthreads();
    if (threadIdx.x == 0) {
        float t = 0.0f;
        #pragma unroll
        for (int i = 0; i < 8; i++) t += ssum[i];
        g_part2[b] = (double)t;
        __threadfence();
        unsigned ticket = atomicAdd(&g_done, 1u);
        slast = (ticket == NB - 1) ? 1 : 0;
        if (slast) g_done = 0;               // reset for next graph replay
    }
    __syncthreads();

    // Last block: deterministic final reduction over L2-warm partials.
    if (slast) {
        __threadfence();                      // make all g_part* writes visible
        __shared__ double sh[256];
        double acc = 0.0;
        const int t = threadIdx.x;
        acc += g_part1[t];
        acc += g_part1[t + 256];
        acc += g_part1[t + 512];
        acc += g_part1[t + 768];
        acc += g_part2[t];
        sh[t] = acc;
        __syncthreads();
        #pragma unroll
        for (int st = 128; st > 0; st >>= 1) {
            if (t < st) sh[t] += sh[t + st];
            __syncthreads();
        }
        if (t == 0)
            res[0] = (float)(sh[0] * (1.0 / (double)NTOT));
    }
}

extern "C" void kernel_launch(void* const* d_in, const int* in_sizes, int n_in,
                              void* d_out, int out_size) {
    const float* outp = (const float*)d_in[0];   // "output" (normal)
    const float* tgtp = (const float*)d_in[1];   // "target" (uniform)
    float* res = (float*)d_out;

    pass1_kernel<<<K1_BLOCKS, 256>>>(outp, tgtp);
    pass2_kernel<<<NB, 256>>>(outp, tgtp, res);
}

// round 6
// speedup vs baseline: 1.0444x; 1.0185x over previous
#include <cuda_runtime.h>
#include <cuda_bf16.h>
#include <cstdint>

// Problem shape
#define NB   256
#define NH   512
#define NW   512
#define HW   (NH * NW)          // 262144 = 1<<18
#define NTOT ((size_t)NB * HW)  // 67108864
#define BPB  4                  // blocks per batch
#define NBLK (NB * BPB)         // 1024 (single wave)
#define CHUNK (HW / BPB)        // 65536 elems per block
#define FWHM 0.5f
#define DHW  32                 // h/H_SCALE = w/W_SCALE = 512/16

// Scratch (no allocations allowed — __device__ globals, zeroed at load)
__device__ unsigned long long g_keyblk[NBLK];  // per-block argmax key
__device__ double   g_part1[NBLK];             // per-block unweighted sqdiff sum
__device__ double   g_part2[NB];               // per-batch window correction
__device__ unsigned g_bdone[NB];               // per-batch ticket (self-resetting)
__device__ unsigned g_done;                    // global ticket  (self-resetting)

// ---------------------------------------------------------------------------
// ONE fused kernel:
//  phase A (all 1024 blocks): stream 64K elems/block of both arrays once;
//     accumulate unweighted sum((o-t)^2) and per-block first-argmax of target.
//     key = (float_bits << 32) | (0xFFFFFFFF - idx): target in [0,1) so uint
//     order == float order; larger ~idx under max => first-max tie-break.
//  phase B (last block of each batch, via per-batch ticket): reduce the
//     batch's 4 keys, re-read the <=64x64 ramp window (L2-HOT — this batch's
//     data was just streamed) and add sqdiff*(vh*vw - 1).
//  phase C (globally last block): deterministic sum of all partials -> mean.
// ---------------------------------------------------------------------------
__global__ __launch_bounds__(256)
void fused_kernel(const float* __restrict__ outp, const float* __restrict__ tgtp,
                  float* __restrict__ res) {
    const int batch = blockIdx.x >> 2;        // / BPB
    const int chunk = blockIdx.x & (BPB - 1);
    const size_t base = (size_t)batch * HW + (size_t)chunk * CHUNK;
    const float4* __restrict__ o4 = (const float4*)(outp + base);
    const float4* __restrict__ t4 = (const float4*)(tgtp + base);
    const unsigned idx0 = (unsigned)(chunk * CHUNK);
    const int tid = threadIdx.x;

    // ---------------- phase A: streaming ----------------
    float s = 0.0f;
    float mval = -1.0f;
    unsigned midx = 0u;

    #pragma unroll 4
    for (int i = tid; i < CHUNK / 4; i += 256) {
        float4 t = t4[i];
        float4 o = o4[i];
        float d0 = o.x - t.x, d1 = o.y - t.y, d2 = o.z - t.z, d3 = o.w - t.w;
        s += d0 * d0 + d1 * d1 + d2 * d2 + d3 * d3;

        float m4 = fmaxf(fmaxf(t.x, t.y), fmaxf(t.z, t.w));
        if (m4 > mval) {                       // rare after warmup
            mval = m4;
            unsigned eb = idx0 + 4u * (unsigned)i;
            midx = (t.x == m4) ? eb
                 : (t.y == m4) ? eb + 1u
                 : (t.z == m4) ? eb + 2u
                 :               eb + 3u;      // in-quad first-match
        }
    }

    unsigned long long bk =
        ((unsigned long long)__float_as_uint(mval) << 32) | (0xFFFFFFFFu - midx);

    #pragma unroll
    for (int off = 16; off > 0; off >>= 1) {
        s += __shfl_down_sync(0xFFFFFFFFu, s, off);
        unsigned long long ok = __shfl_down_sync(0xFFFFFFFFu, bk, off);
        if (ok > bk) bk = ok;
    }

    __shared__ float ssum[8];
    __shared__ unsigned long long skey[8];
    __shared__ int s_fix, s_last;
    const int w = tid >> 5, l = tid & 31;
    if (l == 0) { ssum[w] = s; skey[w] = bk; }
    __syncthreads();

    if (tid == 0) {
        float ts = 0.0f;
        unsigned long long tk = skey[0];
        #pragma unroll
        for (int i = 0; i < 8; i++) {
            ts += ssum[i];
            if (skey[i] > tk) tk = skey[i];
        }
        g_part1[blockIdx.x]  = (double)ts;
        g_keyblk[blockIdx.x] = tk;
        __threadfence();
        unsigned t = atomicAdd(&g_bdone[batch], 1u);
        s_fix = (t == BPB - 1) ? 1 : 0;
        if (s_fix) g_bdone[batch] = 0;         // reset for next graph replay
    }
    __syncthreads();

    // ---------------- phase B: per-batch window fix-up (L2-hot) ----------------
    if (s_fix) {
        __threadfence();  // acquire: other chunks' g_keyblk stores visible
        unsigned long long key = g_keyblk[BPB * batch];
        #pragma unroll
        for (int j = 1; j < BPB; j++) {
            unsigned long long k = g_keyblk[BPB * batch + j];
            if (k > key) key = k;
        }
        const float mv = __uint_as_float((unsigned)(key >> 32));

        float fs = 0.0f;
        if (mv >= FWHM) {
            const unsigned pos = 0xFFFFFFFFu - (unsigned)(key & 0xFFFFFFFFu);
            const int ph = (int)(pos >> 9);
            const int pw = (int)(pos & 511u);
            const int top   = max(ph - DHW, 0);
            const int bot   = min(ph + DHW, NH);
            const int left  = max(pw - DHW, 0);
            const int right = min(pw + DHW, NW);
            const int Lh = bot - top, Lw = right - left;
            const float dh = (float)max((Lh + 1) / 2 - 1, 1);
            const float dw = (float)max((Lw + 1) / 2 - 1, 1);
            const size_t bbase = (size_t)batch << 18;

            const int c  = tid & 63;            // column within window
            const int r0 = tid >> 6;            // 4 row-lanes, stride 4
            float vw = 0.0f;
            if (c < Lw)
                vw = 1.0f + 9.0f * (float)min(c, Lw - 1 - c) / dw;

            if (c < Lw) {
                #pragma unroll
                for (int j = 0; j < 16; j++) {
                    const int r = r0 + 4 * j;
                    if (r < Lh) {
                        const float vh = 1.0f + 9.0f * (float)min(r, Lh - 1 - r) / dh;
                        const size_t idx = bbase + ((size_t)(top + r) << 9)
                                                 + (size_t)(left + c);
                        const float d = outp[idx] - tgtp[idx];
                        fs += d * d * (vh * vw - 1.0f);
                    }
                }
            }
        }

        #pragma unroll
        for (int off = 16; off > 0; off >>= 1)
            fs += __shfl_down_sync(0xFFFFFFFFu, fs, off);
        if (l == 0) ssum[w] = fs;
        __syncthreads();
        if (tid == 0) {
            float t2 = 0.0f;
            #pragma unroll
            for (int i = 0; i < 8; i++) t2 += ssum[i];
            g_part2[batch] = (double)t2;
        }
    }

    // ---------------- phase C: global last block finalizes ----------------
    if (tid == 0) {
        __threadfence();
        unsigned ticket = atomicAdd(&g_done, 1u);
        s_last = (ticket == NBLK - 1) ? 1 : 0;
        if (s_last) g_done = 0;                // reset for next graph replay
    }
    __syncthreads();

    if (s_last) {
        __threadfence();                        // all partials visible
        __shared__ double sh[256];
        double acc = g_part1[tid]
                   + g_part1[tid + 256]
                   + g_part1[tid + 512]
                   + g_part1[tid + 768]
                   + g_part2[tid];
        sh[tid] = acc;
        __syncthreads();
        #pragma unroll
        for (int st = 128; st > 0; st >>= 1) {
            if (tid < st) sh[tid] += sh[tid + st];
            __syncthreads();
        }
        if (tid == 0)
            res[0] = (float)(sh[0] * (1.0 / (double)NTOT));
    }
}

extern "C" void kernel_launch(void* const* d_in, const int* in_sizes, int n_in,
                              void* d_out, int out_size) {
    const float* outp = (const float*)d_in[0];   // "output" (normal)
    const float* tgtp = (const float*)d_in[1];   // "target" (uniform)
    float* res = (float*)d_out;

    fused_kernel<<<NBLK, 256>>>(outp, tgtp, res);
}